// round 1
// baseline (speedup 1.0000x reference)
#include <cuda_runtime.h>
#include <math.h>

#define BB 8
#define SS 2048
#define DM 256
#define NH 4
#define DKK 64
#define NROWS (BB*SS)   // 16384

// ---- scratch (static device, no allocations) ----
__device__ float g_qs[BB*NH*SS*DKK];     // pre-scaled by 1/8
__device__ float g_ks[BB*NH*SS*DKK];
__device__ float g_vs[BB*SS*DKK];
__device__ float g_heads[BB*NH*SS*DKK];

// =====================================================================
// Kernel 1: projections.  grid(128, 9), block 256.
//   y = 0..3 : qs head y (scaled 0.125), 4..7 : ks head y-4, 8 : vs
//   GEMM [16384 x 256] @ W[64 x 256]^T  -> [16384 x 64]
// =====================================================================
__global__ __launch_bounds__(256) void proj_kernel(
    const float* __restrict__ qin, const float* __restrict__ kin,
    const float* __restrict__ vin,
    const float* __restrict__ Wq, const float* __restrict__ bq,
    const float* __restrict__ Wk, const float* __restrict__ bk,
    const float* __restrict__ Wv, const float* __restrict__ bv)
{
    __shared__ float As[8][132];   // transposed A tile [d][row], pad 132
    __shared__ float Bs[8][64];    // transposed W tile [d][e]

    int p = blockIdx.y;
    const float *A, *W, *bias;
    float scale;
    float* dst;
    int h = 0;
    if (p < 4)       { h = p;     A = qin; W = Wq + h*DKK*DM; bias = bq + h*DKK; scale = 0.125f; dst = g_qs; }
    else if (p < 8)  { h = p - 4; A = kin; W = Wk + h*DKK*DM; bias = bk + h*DKK; scale = 1.0f;   dst = g_ks; }
    else             { h = 0;     A = vin; W = Wv;            bias = bv;         scale = 1.0f;   dst = g_vs; }

    int row0 = blockIdx.x * 128;
    int tid = threadIdx.x;
    int tr = tid >> 4;      // 0..15, 8 rows each
    int tc = tid & 15;      // 0..15, 4 cols each

    float acc[8][4];
#pragma unroll
    for (int i = 0; i < 8; i++)
#pragma unroll
        for (int j = 0; j < 4; j++) acc[i][j] = 0.0f;

    for (int d0 = 0; d0 < DM; d0 += 8) {
        __syncthreads();
        {   // A tile: 128 rows x 8 d, transposed into As
            int r = tid >> 1;
            int dblk = (tid & 1) * 4;
            float4 a4 = *(const float4*)(A + (size_t)(row0 + r)*DM + d0 + dblk);
            As[dblk+0][r] = a4.x; As[dblk+1][r] = a4.y;
            As[dblk+2][r] = a4.z; As[dblk+3][r] = a4.w;
        }
        {   // W tile: 64 e x 8 d, transposed into Bs
            int e  = tid & 63;
            int dl = tid >> 6;   // 0..3
            Bs[dl][e]     = W[e*DM + d0 + dl];
            Bs[dl+4][e]   = W[e*DM + d0 + dl + 4];
        }
        __syncthreads();
#pragma unroll
        for (int kk = 0; kk < 8; kk++) {
            float4 a0 = *(float4*)&As[kk][tr*8];
            float4 a1 = *(float4*)&As[kk][tr*8+4];
            float4 w4 = *(float4*)&Bs[kk][tc*4];
            float a[8] = {a0.x,a0.y,a0.z,a0.w,a1.x,a1.y,a1.z,a1.w};
            float w[4] = {w4.x,w4.y,w4.z,w4.w};
#pragma unroll
            for (int i = 0; i < 8; i++)
#pragma unroll
                for (int j = 0; j < 4; j++) acc[i][j] = fmaf(a[i], w[j], acc[i][j]);
        }
    }

    float b4[4];
#pragma unroll
    for (int j = 0; j < 4; j++) b4[j] = bias[tc*4 + j];

#pragma unroll
    for (int i = 0; i < 8; i++) {
        int gr = row0 + tr*8 + i;       // = b*SS + s
        int bb = gr >> 11;
        int s  = gr & (SS-1);
        size_t idx;
        if (p < 8) idx = ((size_t)(bb*NH + h)*SS + s)*DKK + tc*4;
        else       idx = (size_t)gr*DKK + tc*4;
        float4 o;
        o.x = (acc[i][0] + b4[0]) * scale;
        o.y = (acc[i][1] + b4[1]) * scale;
        o.z = (acc[i][2] + b4[2]) * scale;
        o.w = (acc[i][3] + b4[3]) * scale;
        *(float4*)(dst + idx) = o;
    }
}

// =====================================================================
// Kernel 2: fused scores + softmax + attn write + PV.
//   grid(128, 4, 8) = (q-chunk of 16, head, batch), block 256.
//   smem: S_[16][2048] (128KB) + Qs[64][16] + KV(16640f) + invrow[16]
// =====================================================================
#define SMEM2_FLOATS (32768 + 1024 + 16640 + 16)

__global__ __launch_bounds__(256) void attn_kernel(float* __restrict__ attn_out)
{
    extern __shared__ float sm[];
    float* S_     = sm;                    // 16*2048
    float* Qs     = sm + 32768;            // [d][q] 64*16
    float* KV     = sm + 33792;            // KsT[64][260] or Vs[256][64] or red
    float* invrow = sm + 33792 + 16640;    // 16

    int b  = blockIdx.z;
    int h  = blockIdx.y;
    int q0 = blockIdx.x * 16;
    int tid = threadIdx.x;

    const float* qsb = g_qs + ((size_t)(b*NH + h)*SS)*DKK;
    const float* ksb = g_ks + ((size_t)(b*NH + h)*SS)*DKK;
    const float* vsb = g_vs + (size_t)b*SS*DKK;

    // ---- load Q chunk transposed: Qs[d][q] ----
    {
        int qi = tid >> 4;            // 0..15
        int d4 = (tid & 15) * 4;
        float4 v4 = *(const float4*)(qsb + (size_t)(q0 + qi)*DKK + d4);
        Qs[(d4+0)*16 + qi] = v4.x; Qs[(d4+1)*16 + qi] = v4.y;
        Qs[(d4+2)*16 + qi] = v4.z; Qs[(d4+3)*16 + qi] = v4.w;
    }

    // ---- Phase 1: scores S_[q][k] = qs . ks  (already scaled) ----
    int tq = tid >> 6;   // 0..3  (4 q each)
    int tk = tid & 63;   // 0..63 (4 k each)
    for (int kt = 0; kt < 8; kt++) {
        int k0 = kt * 256;
        __syncthreads();
        // load K tile transposed KsT[d][k], pitch 260
#pragma unroll
        for (int i = 0; i < 16; i++) {
            int f4  = tid + i*256;        // 0..4095 float4 slots
            int key = f4 >> 4;
            int d4  = (f4 & 15) * 4;
            float4 v4 = *(const float4*)(ksb + (size_t)(k0 + key)*DKK + d4);
            KV[(d4+0)*260 + key] = v4.x; KV[(d4+1)*260 + key] = v4.y;
            KV[(d4+2)*260 + key] = v4.z; KV[(d4+3)*260 + key] = v4.w;
        }
        __syncthreads();

        float acc[4][4];
#pragma unroll
        for (int i = 0; i < 4; i++)
#pragma unroll
            for (int j = 0; j < 4; j++) acc[i][j] = 0.0f;

#pragma unroll 8
        for (int d = 0; d < 64; d++) {
            float4 q4 = *(float4*)(Qs + d*16 + tq*4);
            float4 k4 = *(float4*)(KV + d*260 + tk*4);
            float qv[4] = {q4.x,q4.y,q4.z,q4.w};
            float kv[4] = {k4.x,k4.y,k4.z,k4.w};
#pragma unroll
            for (int i = 0; i < 4; i++)
#pragma unroll
                for (int j = 0; j < 4; j++) acc[i][j] = fmaf(qv[i], kv[j], acc[i][j]);
        }
#pragma unroll
        for (int i = 0; i < 4; i++) {
            float4 o = make_float4(acc[i][0], acc[i][1], acc[i][2], acc[i][3]);
            *(float4*)(S_ + (size_t)(tq*4 + i)*2048 + k0 + tk*4) = o;
        }
    }
    __syncthreads();

    // ---- Phase 2: softmax (keep unnormalized exp in S_, inv folded later) ----
    {
        int row = tid >> 4;     // 0..15
        int l16 = tid & 15;
        float4* S4 = (float4*)(S_ + row*2048);
        float m = -1e30f;
#pragma unroll 8
        for (int i = 0; i < 32; i++) {
            float4 x = S4[i*16 + l16];
            m = fmaxf(m, fmaxf(fmaxf(x.x, x.y), fmaxf(x.z, x.w)));
        }
#pragma unroll
        for (int off = 8; off >= 1; off >>= 1)
            m = fmaxf(m, __shfl_xor_sync(0xffffffffu, m, off));
        float ssum = 0.0f;
#pragma unroll 4
        for (int i = 0; i < 32; i++) {
            int idx = i*16 + l16;
            float4 x = S4[idx];
            x.x = __expf(x.x - m); x.y = __expf(x.y - m);
            x.z = __expf(x.z - m); x.w = __expf(x.w - m);
            S4[idx] = x;
            ssum += (x.x + x.y) + (x.z + x.w);
        }
#pragma unroll
        for (int off = 8; off >= 1; off >>= 1)
            ssum += __shfl_xor_sync(0xffffffffu, ssum, off);
        if (l16 == 0) invrow[row] = 1.0f / ssum;
    }
    __syncthreads();

    // ---- Phase 2b: normalized attn -> gmem ----
    {
        float* ab = attn_out + (((size_t)b*SS + q0)*NH + h)*SS;
#pragma unroll 4
        for (int it = 0; it < 32; it++) {
            int slot = tid + it*256;         // 0..8191 float4 slots
            int r  = slot >> 9;              // /512
            int c4 = slot & 511;
            float4 x = ((float4*)(S_ + r*2048))[c4];
            float inv = invrow[r];
            x.x *= inv; x.y *= inv; x.z *= inv; x.w *= inv;
            ((float4*)(ab + (size_t)r*NH*SS))[c4] = x;
        }
    }

    // ---- Phase 3: PV  o[q][e] = sum_k p~[q][k] * vs[k][e], k split 4-way ----
    int kg  = tid >> 6;       // 0..3 k-quarter
    int sub = tid & 63;
    int tq2 = sub >> 4;       // 0..3 (4 q each)
    int te  = sub & 15;       // 0..15 (4 e each)
    float acc2[4][4];
#pragma unroll
    for (int i = 0; i < 4; i++)
#pragma unroll
        for (int j = 0; j < 4; j++) acc2[i][j] = 0.0f;

    for (int vt = 0; vt < 8; vt++) {
        int k0 = vt * 256;
        __syncthreads();
        // load V tile linear: Vs[k][e] (straight float4 copy)
        {
            const float4* src = (const float4*)(vsb + (size_t)k0*DKK);
            float4* dst4 = (float4*)KV;
#pragma unroll
            for (int i = 0; i < 16; i++) {
                int f4 = tid + i*256;
                dst4[f4] = src[f4];
            }
        }
        __syncthreads();
#pragma unroll 8
        for (int kk = 0; kk < 64; kk++) {
            int kl = kg*64 + kk;
            float4 v4 = ((float4*)KV)[kl*16 + te];
#pragma unroll
            for (int j = 0; j < 4; j++) {
                float pp = S_[(size_t)(tq2*4 + j)*2048 + k0 + kl];
                acc2[j][0] = fmaf(pp, v4.x, acc2[j][0]);
                acc2[j][1] = fmaf(pp, v4.y, acc2[j][1]);
                acc2[j][2] = fmaf(pp, v4.z, acc2[j][2]);
                acc2[j][3] = fmaf(pp, v4.w, acc2[j][3]);
            }
        }
    }
    __syncthreads();
    // reduce the 4 k-quarters through smem (red = KV)
    {
        float* red = KV;   // 4*16*64 = 4096 floats
#pragma unroll
        for (int j = 0; j < 4; j++) {
            float4 o = make_float4(acc2[j][0], acc2[j][1], acc2[j][2], acc2[j][3]);
            *(float4*)(red + (size_t)((kg*16 + tq2*4 + j)*64 + te*4)) = o;
        }
    }
    __syncthreads();
    {
        float* red = KV;
        int qq = tid >> 4;     // 0..15
        int e4 = tid & 15;
        float4 o = make_float4(0.f, 0.f, 0.f, 0.f);
#pragma unroll
        for (int g = 0; g < 4; g++) {
            float4 t = ((float4*)red)[(g*16 + qq)*16 + e4];
            o.x += t.x; o.y += t.y; o.z += t.z; o.w += t.w;
        }
        float inv = invrow[qq];
        o.x *= inv; o.y *= inv; o.z *= inv; o.w *= inv;
        *(float4*)(g_heads + ((size_t)(b*NH + h)*SS + q0 + qq)*DKK + e4*4) = o;
    }
}

// =====================================================================
// Kernel 3: head-average + output projection.
//   grid(256), block 256.  out[s][dm] = sum_e avg[s][e] * Wh[dm][e]
// =====================================================================
#define SMEM3_FLOATS (64*68 + 64*260)

__global__ __launch_bounds__(256) void outproj_kernel(
    const float* __restrict__ Wh, float* __restrict__ out)
{
    extern __shared__ float sm[];
    float* AvT = sm;             // [e][s] 64x68
    float* WhT = sm + 64*68;     // [e][dm] 64x260

    int s0 = blockIdx.x * 64;
    int tid = threadIdx.x;

    // head-average: 64 rows x 64 e
#pragma unroll
    for (int i = 0; i < 16; i++) {
        int idx = tid + i*256;            // 0..4095
        int sl = idx >> 6, e = idx & 63;
        int gr = s0 + sl;
        int bb = gr >> 11, s = gr & (SS-1);
        size_t base = ((size_t)bb*NH*SS + s)*DKK + e;
        float sum = g_heads[base]
                  + g_heads[base + (size_t)SS*DKK]
                  + g_heads[base + (size_t)2*SS*DKK]
                  + g_heads[base + (size_t)3*SS*DKK];
        AvT[e*68 + sl] = 0.25f * sum;
    }
    // Wh transposed
#pragma unroll
    for (int i = 0; i < 64; i++) {
        int idx = tid + i*256;            // 0..16383
        int dm = idx >> 6, e = idx & 63;
        WhT[e*260 + dm] = Wh[dm*DKK + e];
    }
    __syncthreads();

    int ts = tid >> 5;   // 0..7  (8 s each)
    int tc = tid & 31;   // 0..31 (8 dm each)
    float acc[8][8];
#pragma unroll
    for (int i = 0; i < 8; i++)
#pragma unroll
        for (int j = 0; j < 8; j++) acc[i][j] = 0.0f;

#pragma unroll 8
    for (int e = 0; e < 64; e++) {
        float4 a0 = *(float4*)(AvT + e*68 + ts*8);
        float4 a1 = *(float4*)(AvT + e*68 + ts*8 + 4);
        float4 w0 = *(float4*)(WhT + e*260 + tc*8);
        float4 w1 = *(float4*)(WhT + e*260 + tc*8 + 4);
        float a[8] = {a0.x,a0.y,a0.z,a0.w,a1.x,a1.y,a1.z,a1.w};
        float w[8] = {w0.x,w0.y,w0.z,w0.w,w1.x,w1.y,w1.z,w1.w};
#pragma unroll
        for (int i = 0; i < 8; i++)
#pragma unroll
            for (int j = 0; j < 8; j++) acc[i][j] = fmaf(a[i], w[j], acc[i][j]);
    }
#pragma unroll
    for (int i = 0; i < 8; i++) {
        int gr = s0 + ts*8 + i;
        float4 o0 = make_float4(acc[i][0], acc[i][1], acc[i][2], acc[i][3]);
        float4 o1 = make_float4(acc[i][4], acc[i][5], acc[i][6], acc[i][7]);
        *(float4*)(out + (size_t)gr*DM + tc*8)     = o0;
        *(float4*)(out + (size_t)gr*DM + tc*8 + 4) = o1;
    }
}

// =====================================================================
extern "C" void kernel_launch(void* const* d_in, const int* in_sizes, int n_in,
                              void* d_out, int out_size)
{
    const float* q  = (const float*)d_in[0];
    const float* k  = (const float*)d_in[1];
    const float* v  = (const float*)d_in[2];
    const float* Wq = (const float*)d_in[3];
    const float* bq = (const float*)d_in[4];
    const float* Wk = (const float*)d_in[5];
    const float* bk = (const float*)d_in[6];
    const float* Wv = (const float*)d_in[7];
    const float* bv = (const float*)d_in[8];
    const float* Wh = (const float*)d_in[9];

    float* out  = (float*)d_out;                       // [B,S,DM]
    float* attn = out + (size_t)BB*SS*DM;              // [B,S,H,S]

    cudaFuncSetAttribute(attn_kernel, cudaFuncAttributeMaxDynamicSharedMemorySize,
                         SMEM2_FLOATS * sizeof(float));
    cudaFuncSetAttribute(outproj_kernel, cudaFuncAttributeMaxDynamicSharedMemorySize,
                         SMEM3_FLOATS * sizeof(float));

    proj_kernel<<<dim3(NROWS/128, 9), 256>>>(q, k, v, Wq, bq, Wk, bk, Wv, bv);
    attn_kernel<<<dim3(SS/16, NH, BB), 256, SMEM2_FLOATS * sizeof(float)>>>(attn);
    outproj_kernel<<<NROWS/64, 256, SMEM3_FLOATS * sizeof(float)>>>(Wh, out);
}